// round 6
// baseline (speedup 1.0000x reference)
#include <cuda_runtime.h>

#define N_GENES 768
#define HID 128

// Scratch (__device__ globals per alloc rules)
__device__ float g_P[N_GENES * HID];    // X @ W1[:, :H].T + b1  (i-side, bias folded)
__device__ float g_Q[N_GENES * HID];    // X @ W1[:, H:].T       (j-side)
__device__ float g_Y[N_GENES * HID];    // X @ Wb[0]             (bilinear left product)
__device__ float g_W1T[2 * HID * HID];  // W1 transposed: g_W1T[m][c] = W1[c][m]

// ---- packed fp32x2 helpers (Blackwell FFMA2 — only reachable via PTX) ----
union F2U { float2 f; unsigned long long u; };

__device__ __forceinline__ float2 fadd2(float2 a, float2 b) {
    F2U ua, ub, r; ua.f = a; ub.f = b;
    asm("add.rn.f32x2 %0, %1, %2;" : "=l"(r.u) : "l"(ua.u), "l"(ub.u));
    return r.f;
}
__device__ __forceinline__ float2 ffma2(float2 a, float2 b, float2 c) {
    F2U ua, ub, uc, r; ua.f = a; ub.f = b; uc.f = c;
    asm("fma.rn.f32x2 %0, %1, %2, %3;" : "=l"(r.u) : "l"(ua.u), "l"(ub.u), "l"(uc.u));
    return r.f;
}
__device__ __forceinline__ float2 relu2(float2 a) {
    // FMNMX -> ALU pipe, overlaps packed FMA-pipe math
    return make_float2(fmaxf(a.x, 0.f), fmaxf(a.y, 0.f));
}

// ---------------------------------------------------------------------------
// Transpose W1 [128][256] -> g_W1T [256][128]. Coalesced read AND write via
// 32x32 smem tile. grid (8, 4), block (32, 8).
// ---------------------------------------------------------------------------
__global__ void grn_transposeW1(const float* __restrict__ W1) {
    __shared__ float tile[32][33];
    const int x = threadIdx.x;          // 0..31
    const int y = threadIdx.y;          // 0..7
    const int col0 = blockIdx.x * 32;   // W1 column block (0..255 range)
    const int row0 = blockIdx.y * 32;   // W1 row block    (0..127 range)

#pragma unroll
    for (int k = 0; k < 4; k++)
        tile[y + k * 8][x] = W1[(row0 + y + k * 8) * (2 * HID) + col0 + x];
    __syncthreads();
#pragma unroll
    for (int k = 0; k < 4; k++)
        g_W1T[(col0 + y + k * 8) * HID + row0 + x] = tile[x][y + k * 8];
}

// ---------------------------------------------------------------------------
// Precompute P(+b1), Q, Y.  96 blocks x 256 threads, 8 genes/block.
// Thread t: output column c = t&127. m-major loop; ALL gmem loads coalesced:
// g_W1T[m][c], g_W1T[HID+m][c], Wb[m][c] (contraction over Wb's first index).
// This is the R3 structure with the transpose done for real this time.
// ---------------------------------------------------------------------------
__global__ __launch_bounds__(256) void grn_precompute(
    const float* __restrict__ X,
    const float* __restrict__ b1,
    const float* __restrict__ Wb)
{
    __shared__ float XsT[HID][8];       // transposed X tile: XsT[m][g]
    const int t  = threadIdx.x;
    const int c  = t & 127;             // output column
    const int gh = (t >> 7) * 4;        // gene sub-offset: 0 or 4
    const int g0 = blockIdx.x * 8;

    for (int idx = t; idx < 8 * HID; idx += 256) {
        const int g = idx >> 7, m = idx & 127;   // coalesced X read
        XsT[m][g] = X[(g0 + g) * HID + m];
    }
    __syncthreads();

    const float bias = b1[c];
    float accP[4], accQ[4], accY[4];
#pragma unroll
    for (int g = 0; g < 4; g++) { accP[g] = bias; accQ[g] = 0.f; accY[g] = 0.f; }

#pragma unroll 16
    for (int m = 0; m < HID; m++) {
        const float w1a = g_W1T[m * HID + c];          // coalesced
        const float w1b = g_W1T[(HID + m) * HID + c];  // coalesced
        const float wb  = __ldg(&Wb[m * HID + c]);     // coalesced
        const float4 xv = *(const float4*)&XsT[m][gh]; // broadcast LDS.128
        const float xa[4] = {xv.x, xv.y, xv.z, xv.w};
#pragma unroll
        for (int g = 0; g < 4; g++) {
            accP[g] = fmaf(xa[g], w1a, accP[g]);
            accQ[g] = fmaf(xa[g], w1b, accQ[g]);
            accY[g] = fmaf(xa[g], wb,  accY[g]);
        }
    }
#pragma unroll
    for (int g = 0; g < 4; g++) {
        g_P[(g0 + gh + g) * HID + c] = accP[g];   // coalesced stores
        g_Q[(g0 + gh + g) * HID + c] = accQ[g];
        g_Y[(g0 + gh + g) * HID + c] = accY[g];
    }
}

// ---------------------------------------------------------------------------
// Pair kernel: block 16x16 threads, output tile 64(i) x 64(j),
// microtile 4i x 4j per thread (j packed into f32x2 pairs -> FFMA2).
// LOGIT-DIFFERENCE trick: accumulate D0 = L0-L1 and D2 = L2-L1 with
// pre-differenced weights (w0-w1), (w2-w1) -> 32 FMA-pipe instrs/kk (was 40),
// 2 weight LDS (was 3), 48 accumulator regs (was 64).
//   cls==0  <=>  D0>=0 && D0>=D2        cls==2  <=>  D2>D0 && D2>0
// ---------------------------------------------------------------------------
__global__ __launch_bounds__(256) void grn_pairs(
    const float* __restrict__ X,
    const float* __restrict__ W2,
    const float* __restrict__ b2,
    const float* __restrict__ bb,
    float* __restrict__ out)
{
    __shared__ float Ps[32][136];   // [kk][2*i_local (dup)]  stride 544B
    __shared__ float Ys[32][136];
    __shared__ float Qs[32][72];    // [kk][j_local]          stride 288B
    __shared__ float Xs[32][72];
    __shared__ float Wd[2][2 * HID];  // [0]=w0-w1 dup, [1]=w2-w1 dup

    const int tx = threadIdx.x;     // 0..15 -> j microtile base 4*tx
    const int ty = threadIdx.y;     // 0..15 -> i microtile base 4*ty
    const int t  = ty * 16 + tx;
    const int i0 = blockIdx.y * 64;
    const int j0 = blockIdx.x * 64;

    // pre-differenced, duplicated weight fill
    if (t < HID) {
        const float w0 = W2[t];
        const float w1 = W2[HID + t];
        const float w2 = W2[2 * HID + t];
        const float d0 = w0 - w1;
        const float d2 = w2 - w1;
        Wd[0][2 * t]     = d0;
        Wd[0][2 * t + 1] = d0;
        Wd[1][2 * t]     = d2;
        Wd[1][2 * t + 1] = d2;
    }

    float2 D0[4][2], D2[4][2], af[4][2];
#pragma unroll
    for (int r = 0; r < 4; r++)
#pragma unroll
        for (int p = 0; p < 2; p++) {
            D0[r][p] = make_float2(0.f, 0.f);
            D2[r][p] = make_float2(0.f, 0.f);
            af[r][p] = make_float2(0.f, 0.f);
        }

    const int ri = t >> 2;          // 0..63 : local row for fills
    const int kq = (t & 3) * 8;     // k offset within chunk (8 values/thread)

    for (int kc = 0; kc < HID; kc += 32) {
        // issue GMEM loads before the barrier so latency overlaps prior compute
        const float4 vp0 = *(const float4*)&g_P[(i0 + ri) * HID + kc + kq];
        const float4 vp1 = *(const float4*)&g_P[(i0 + ri) * HID + kc + kq + 4];
        const float4 vy0 = *(const float4*)&g_Y[(i0 + ri) * HID + kc + kq];
        const float4 vy1 = *(const float4*)&g_Y[(i0 + ri) * HID + kc + kq + 4];
        const float4 vq0 = *(const float4*)&g_Q[(j0 + ri) * HID + kc + kq];
        const float4 vq1 = *(const float4*)&g_Q[(j0 + ri) * HID + kc + kq + 4];
        const float4 vx0 = *(const float4*)&X[(j0 + ri) * HID + kc + kq];
        const float4 vx1 = *(const float4*)&X[(j0 + ri) * HID + kc + kq + 4];

        __syncthreads();   // prior compute done -> safe to overwrite smem

        {
            const float pv[8] = {vp0.x, vp0.y, vp0.z, vp0.w, vp1.x, vp1.y, vp1.z, vp1.w};
            const float yv[8] = {vy0.x, vy0.y, vy0.z, vy0.w, vy1.x, vy1.y, vy1.z, vy1.w};
#pragma unroll
            for (int l = 0; l < 8; l++) {
                // duplicated pair via single STS.64
                *(float2*)&Ps[kq + l][2 * ri] = make_float2(pv[l], pv[l]);
                *(float2*)&Ys[kq + l][2 * ri] = make_float2(yv[l], yv[l]);
            }
            const float qv[8] = {vq0.x, vq0.y, vq0.z, vq0.w, vq1.x, vq1.y, vq1.z, vq1.w};
            const float xw[8] = {vx0.x, vx0.y, vx0.z, vx0.w, vx1.x, vx1.y, vx1.z, vx1.w};
#pragma unroll
            for (int l = 0; l < 8; l++) {
                Qs[kq + l][ri] = qv[l];
                Xs[kq + l][ri] = xw[l];
            }
        }
        __syncthreads();

#pragma unroll
        for (int kk = 0; kk < 32; kk++) {
            const float4 ap0 = *(const float4*)&Ps[kk][8 * ty];       // i0,i0,i1,i1
            const float4 ap1 = *(const float4*)&Ps[kk][8 * ty + 4];   // i2,i2,i3,i3
            const float4 yp0 = *(const float4*)&Ys[kk][8 * ty];
            const float4 yp1 = *(const float4*)&Ys[kk][8 * ty + 4];
            const float4 qv  = *(const float4*)&Qs[kk][4 * tx];
            const float4 xv  = *(const float4*)&Xs[kk][4 * tx];

            const float2 wd0 = *(const float2*)&Wd[0][2 * (kc + kk)];
            const float2 wd2 = *(const float2*)&Wd[1][2 * (kc + kk)];

            const float2 q01 = make_float2(qv.x, qv.y);
            const float2 q23 = make_float2(qv.z, qv.w);
            const float2 x01 = make_float2(xv.x, xv.y);
            const float2 x23 = make_float2(xv.z, xv.w);

            const float2 av[4] = { make_float2(ap0.x, ap0.y), make_float2(ap0.z, ap0.w),
                                   make_float2(ap1.x, ap1.y), make_float2(ap1.z, ap1.w) };
            const float2 yv[4] = { make_float2(yp0.x, yp0.y), make_float2(yp0.z, yp0.w),
                                   make_float2(yp1.x, yp1.y), make_float2(yp1.z, yp1.w) };

#pragma unroll
            for (int r = 0; r < 4; r++) {
                const float2 h0 = relu2(fadd2(av[r], q01));
                const float2 h1 = relu2(fadd2(av[r], q23));
                D0[r][0] = ffma2(h0, wd0, D0[r][0]);
                D0[r][1] = ffma2(h1, wd0, D0[r][1]);
                D2[r][0] = ffma2(h0, wd2, D2[r][0]);
                D2[r][1] = ffma2(h1, wd2, D2[r][1]);
                af[r][0] = ffma2(yv[r], x01, af[r][0]);
                af[r][1] = ffma2(yv[r], x23, af[r][1]);
            }
        }
    }

    const float db0 = b2[0] - b2[1];   // bias of D0
    const float db2 = b2[2] - b2[1];   // bias of D2
    const float bb0 = bb[0];

#pragma unroll
    for (int r = 0; r < 4; r++) {
        const int i = i0 + 4 * ty + r;
        float vals[4];
#pragma unroll
        for (int p = 0; p < 2; p++) {
            const float2 d0v = D0[r][p], d2v = D2[r][p], A = af[r][p];
#pragma unroll
            for (int half = 0; half < 2; half++) {
                const float e0 = (half ? d0v.y : d0v.x) + db0;   // L0 - L1
                const float e2 = (half ? d2v.y : d2v.x) + db2;   // L2 - L1
                // first-occurrence argmax (matches jnp.argmax):
                //   cls0 <=> L0>=L1 && L0>=L2 ; cls2 <=> L2>L0 && L2>L1
                float s = 0.f;
                if (e0 >= 0.f && e0 >= e2)     s = 1.f;
                else if (e2 > e0 && e2 > 0.f)  s = -1.f;
                const int j = j0 + 4 * tx + 2 * p + half;
                float v = s * ((half ? A.y : A.x) + bb0);
                if (i == j) v = 0.f;
                vals[2 * p + half] = v;
            }
        }
        *(float4*)&out[i * N_GENES + j0 + 4 * tx] =
            make_float4(vals[0], vals[1], vals[2], vals[3]);
    }
}

extern "C" void kernel_launch(void* const* d_in, const int* in_sizes, int n_in,
                              void* d_out, int out_size) {
    (void)in_sizes; (void)n_in; (void)out_size;
    const float* X  = (const float*)d_in[0];  // gene_embeddings [768,128]
    const float* W1 = (const float*)d_in[1];  // [128,256]
    const float* b1 = (const float*)d_in[2];  // [128]
    const float* W2 = (const float*)d_in[3];  // [3,128]
    const float* b2 = (const float*)d_in[4];  // [3]
    const float* Wb = (const float*)d_in[5];  // [1,128,128]
    const float* bb = (const float*)d_in[6];  // [1]
    float* out = (float*)d_out;               // [768,768]

    grn_transposeW1<<<dim3(8, 4), dim3(32, 8)>>>(W1);
    grn_precompute<<<N_GENES / 8, 256>>>(X, b1, Wb);
    grn_pairs<<<dim3(N_GENES / 64, N_GENES / 64), dim3(16, 16)>>>(X, W2, b2, bb, out);
}

// round 7
// speedup vs baseline: 1.1804x; 1.1804x over previous
#include <cuda_runtime.h>

#define N_GENES 768
#define HID 128

// Scratch (__device__ globals per alloc rules)
__device__ float g_P[N_GENES * HID];    // X @ W1[:, :H].T + b1  (i-side, bias folded)
__device__ float g_Q[N_GENES * HID];    // X @ W1[:, H:].T       (j-side)
__device__ float g_Y[N_GENES * HID];    // X @ Wb[0]             (bilinear left product)

// ---- packed fp32x2 helpers (Blackwell FFMA2 — only reachable via PTX) ----
union F2U { float2 f; unsigned long long u; };

__device__ __forceinline__ float2 fadd2(float2 a, float2 b) {
    F2U ua, ub, r; ua.f = a; ub.f = b;
    asm("add.rn.f32x2 %0, %1, %2;" : "=l"(r.u) : "l"(ua.u), "l"(ub.u));
    return r.f;
}
__device__ __forceinline__ float2 ffma2(float2 a, float2 b, float2 c) {
    F2U ua, ub, uc, r; ua.f = a; ub.f = b; uc.f = c;
    asm("fma.rn.f32x2 %0, %1, %2, %3;" : "=l"(r.u) : "l"(ua.u), "l"(ub.u), "l"(uc.u));
    return r.f;
}
__device__ __forceinline__ float2 relu2(float2 a) {
    // FMNMX -> ALU pipe, overlaps packed FMA-pipe math
    return make_float2(fmaxf(a.x, 0.f), fmaxf(a.y, 0.f));
}

// ---------------------------------------------------------------------------
// Precompute P(+b1), Q, Y with the W1 transpose FUSED via smem chunk staging
// (R6's separate transpose kernel cost 4.3us of pure launch overhead).
// 96 blocks x 256 threads, 8 genes/block. Thread t: column c = t&127,
// genes gh..gh+3. Per 32-m chunk: stage WsA[mm][c]=W1[c][mc+mm] (coalesced
// float4 gmem reads, conflict-free stride-133 smem writes), then m-major
// compute with conflict-free lane-consecutive smem reads + coalesced Wb LDG.
// ---------------------------------------------------------------------------
__global__ __launch_bounds__(256) void grn_precompute(
    const float* __restrict__ X,
    const float* __restrict__ W1,
    const float* __restrict__ b1,
    const float* __restrict__ Wb)
{
    __shared__ float XsT[HID][8];       // XsT[m][g] (row 32B -> float4-aligned)
    __shared__ float WsA[32][133];      // WsA[mm][c] = W1[c][mc+mm]
    __shared__ float WsB[32][133];      // WsB[mm][c] = W1[c][HID+mc+mm]

    const int t  = threadIdx.x;
    const int c  = t & 127;             // output column == W1 row
    const int gh = (t >> 7) * 4;        // gene sub-offset: 0 or 4
    const int g0 = blockIdx.x * 8;

    for (int idx = t; idx < 8 * HID; idx += 256) {
        const int g = idx >> 7, m = idx & 127;   // coalesced X read
        XsT[m][g] = X[(g0 + g) * HID + m];
    }

    const float bias = b1[c];
    float accP[4], accQ[4], accY[4];
#pragma unroll
    for (int g = 0; g < 4; g++) { accP[g] = bias; accQ[g] = 0.f; accY[g] = 0.f; }

    for (int mc = 0; mc < HID; mc += 32) {
        __syncthreads();   // protect prior-chunk smem reads (also orders XsT fill)

        // stage both W1 halves for this chunk: 1024 float4 per half, 4/thread
#pragma unroll
        for (int f = 0; f < 4; f++) {
            const int fid = t + f * 256;          // 0..1023
            const int cr  = fid >> 3;             // W1 row 0..127
            const int q   = fid & 7;              // float4 within 32-float chunk
            const float4 va = *(const float4*)&W1[cr * (2 * HID) + mc + 4 * q];
            const float4 vb = *(const float4*)&W1[cr * (2 * HID) + HID + mc + 4 * q];
            WsA[4 * q + 0][cr] = va.x; WsA[4 * q + 1][cr] = va.y;
            WsA[4 * q + 2][cr] = va.z; WsA[4 * q + 3][cr] = va.w;
            WsB[4 * q + 0][cr] = vb.x; WsB[4 * q + 1][cr] = vb.y;
            WsB[4 * q + 2][cr] = vb.z; WsB[4 * q + 3][cr] = vb.w;
        }
        __syncthreads();

#pragma unroll 8
        for (int mm = 0; mm < 32; mm++) {
            const int m = mc + mm;
            const float w1a = WsA[mm][c];              // lane-consecutive: conflict-free
            const float w1b = WsB[mm][c];
            const float wb  = __ldg(&Wb[m * HID + c]); // coalesced
            const float4 xv = *(const float4*)&XsT[m][gh]; // broadcast LDS.128
            const float xa[4] = {xv.x, xv.y, xv.z, xv.w};
#pragma unroll
            for (int g = 0; g < 4; g++) {
                accP[g] = fmaf(xa[g], w1a, accP[g]);
                accQ[g] = fmaf(xa[g], w1b, accQ[g]);
                accY[g] = fmaf(xa[g], wb,  accY[g]);
            }
        }
    }
#pragma unroll
    for (int g = 0; g < 4; g++) {
        g_P[(g0 + gh + g) * HID + c] = accP[g];   // coalesced stores
        g_Q[(g0 + gh + g) * HID + c] = accQ[g];
        g_Y[(g0 + gh + g) * HID + c] = accY[g];
    }
}

// ---------------------------------------------------------------------------
// Pair kernel (unchanged from R6): block 16x16, tile 64x64, microtile 4i x 4j
// (j packed f32x2 -> FFMA2). Logit-difference trick: D0=L0-L1, D2=L2-L1 with
// pre-differenced weights -> 32 FMA-pipe instrs/kk, 2 weight LDS, 48 acc regs.
// ---------------------------------------------------------------------------
__global__ __launch_bounds__(256) void grn_pairs(
    const float* __restrict__ X,
    const float* __restrict__ W2,
    const float* __restrict__ b2,
    const float* __restrict__ bb,
    float* __restrict__ out)
{
    __shared__ float Ps[32][136];   // [kk][2*i_local (dup)]
    __shared__ float Ys[32][136];
    __shared__ float Qs[32][72];    // [kk][j_local]
    __shared__ float Xs[32][72];
    __shared__ float Wd[2][2 * HID];  // [0]=w0-w1 dup, [1]=w2-w1 dup

    const int tx = threadIdx.x;
    const int ty = threadIdx.y;
    const int t  = ty * 16 + tx;
    const int i0 = blockIdx.y * 64;
    const int j0 = blockIdx.x * 64;

    if (t < HID) {
        const float w0 = W2[t];
        const float w1 = W2[HID + t];
        const float w2 = W2[2 * HID + t];
        const float d0 = w0 - w1;
        const float d2 = w2 - w1;
        Wd[0][2 * t]     = d0;
        Wd[0][2 * t + 1] = d0;
        Wd[1][2 * t]     = d2;
        Wd[1][2 * t + 1] = d2;
    }

    float2 D0[4][2], D2[4][2], af[4][2];
#pragma unroll
    for (int r = 0; r < 4; r++)
#pragma unroll
        for (int p = 0; p < 2; p++) {
            D0[r][p] = make_float2(0.f, 0.f);
            D2[r][p] = make_float2(0.f, 0.f);
            af[r][p] = make_float2(0.f, 0.f);
        }

    const int ri = t >> 2;
    const int kq = (t & 3) * 8;

    for (int kc = 0; kc < HID; kc += 32) {
        const float4 vp0 = *(const float4*)&g_P[(i0 + ri) * HID + kc + kq];
        const float4 vp1 = *(const float4*)&g_P[(i0 + ri) * HID + kc + kq + 4];
        const float4 vy0 = *(const float4*)&g_Y[(i0 + ri) * HID + kc + kq];
        const float4 vy1 = *(const float4*)&g_Y[(i0 + ri) * HID + kc + kq + 4];
        const float4 vq0 = *(const float4*)&g_Q[(j0 + ri) * HID + kc + kq];
        const float4 vq1 = *(const float4*)&g_Q[(j0 + ri) * HID + kc + kq + 4];
        const float4 vx0 = *(const float4*)&X[(j0 + ri) * HID + kc + kq];
        const float4 vx1 = *(const float4*)&X[(j0 + ri) * HID + kc + kq + 4];

        __syncthreads();

        {
            const float pv[8] = {vp0.x, vp0.y, vp0.z, vp0.w, vp1.x, vp1.y, vp1.z, vp1.w};
            const float yv[8] = {vy0.x, vy0.y, vy0.z, vy0.w, vy1.x, vy1.y, vy1.z, vy1.w};
#pragma unroll
            for (int l = 0; l < 8; l++) {
                *(float2*)&Ps[kq + l][2 * ri] = make_float2(pv[l], pv[l]);
                *(float2*)&Ys[kq + l][2 * ri] = make_float2(yv[l], yv[l]);
            }
            const float qv[8] = {vq0.x, vq0.y, vq0.z, vq0.w, vq1.x, vq1.y, vq1.z, vq1.w};
            const float xw[8] = {vx0.x, vx0.y, vx0.z, vx0.w, vx1.x, vx1.y, vx1.z, vx1.w};
#pragma unroll
            for (int l = 0; l < 8; l++) {
                Qs[kq + l][ri] = qv[l];
                Xs[kq + l][ri] = xw[l];
            }
        }
        __syncthreads();

#pragma unroll
        for (int kk = 0; kk < 32; kk++) {
            const float4 ap0 = *(const float4*)&Ps[kk][8 * ty];
            const float4 ap1 = *(const float4*)&Ps[kk][8 * ty + 4];
            const float4 yp0 = *(const float4*)&Ys[kk][8 * ty];
            const float4 yp1 = *(const float4*)&Ys[kk][8 * ty + 4];
            const float4 qv  = *(const float4*)&Qs[kk][4 * tx];
            const float4 xv  = *(const float4*)&Xs[kk][4 * tx];

            const float2 wd0 = *(const float2*)&Wd[0][2 * (kc + kk)];
            const float2 wd2 = *(const float2*)&Wd[1][2 * (kc + kk)];

            const float2 q01 = make_float2(qv.x, qv.y);
            const float2 q23 = make_float2(qv.z, qv.w);
            const float2 x01 = make_float2(xv.x, xv.y);
            const float2 x23 = make_float2(xv.z, xv.w);

            const float2 av[4] = { make_float2(ap0.x, ap0.y), make_float2(ap0.z, ap0.w),
                                   make_float2(ap1.x, ap1.y), make_float2(ap1.z, ap1.w) };
            const float2 yv[4] = { make_float2(yp0.x, yp0.y), make_float2(yp0.z, yp0.w),
                                   make_float2(yp1.x, yp1.y), make_float2(yp1.z, yp1.w) };

#pragma unroll
            for (int r = 0; r < 4; r++) {
                const float2 h0 = relu2(fadd2(av[r], q01));
                const float2 h1 = relu2(fadd2(av[r], q23));
                D0[r][0] = ffma2(h0, wd0, D0[r][0]);
                D0[r][1] = ffma2(h1, wd0, D0[r][1]);
                D2[r][0] = ffma2(h0, wd2, D2[r][0]);
                D2[r][1] = ffma2(h1, wd2, D2[r][1]);
                af[r][0] = ffma2(yv[r], x01, af[r][0]);
                af[r][1] = ffma2(yv[r], x23, af[r][1]);
            }
        }
    }

    const float db0 = b2[0] - b2[1];
    const float db2 = b2[2] - b2[1];
    const float bb0 = bb[0];

#pragma unroll
    for (int r = 0; r < 4; r++) {
        const int i = i0 + 4 * ty + r;
        float vals[4];
#pragma unroll
        for (int p = 0; p < 2; p++) {
            const float2 d0v = D0[r][p], d2v = D2[r][p], A = af[r][p];
#pragma unroll
            for (int half = 0; half < 2; half++) {
                const float e0 = (half ? d0v.y : d0v.x) + db0;   // L0 - L1
                const float e2 = (half ? d2v.y : d2v.x) + db2;   // L2 - L1
                // first-occurrence argmax (matches jnp.argmax)
                float s = 0.f;
                if (e0 >= 0.f && e0 >= e2)     s = 1.f;
                else if (e2 > e0 && e2 > 0.f)  s = -1.f;
                const int j = j0 + 4 * tx + 2 * p + half;
                float v = s * ((half ? A.y : A.x) + bb0);
                if (i == j) v = 0.f;
                vals[2 * p + half] = v;
            }
        }
        *(float4*)&out[i * N_GENES + j0 + 4 * tx] =
            make_float4(vals[0], vals[1], vals[2], vals[3]);
    }
}

extern "C" void kernel_launch(void* const* d_in, const int* in_sizes, int n_in,
                              void* d_out, int out_size) {
    (void)in_sizes; (void)n_in; (void)out_size;
    const float* X  = (const float*)d_in[0];  // gene_embeddings [768,128]
    const float* W1 = (const float*)d_in[1];  // [128,256]
    const float* b1 = (const float*)d_in[2];  // [128]
    const float* W2 = (const float*)d_in[3];  // [3,128]
    const float* b2 = (const float*)d_in[4];  // [3]
    const float* Wb = (const float*)d_in[5];  // [1,128,128]
    const float* bb = (const float*)d_in[6];  // [1]
    float* out = (float*)d_out;               // [768,768]

    grn_precompute<<<N_GENES / 8, 256>>>(X, W1, b1, Wb);
    grn_pairs<<<dim3(N_GENES / 64, N_GENES / 64), dim3(16, 16)>>>(X, W2, b2, bb, out);
}